// round 3
// baseline (speedup 1.0000x reference)
#include <cuda_runtime.h>
#include <cstdint>

// SpikeFP8MulToFP32:
//   A, B: [N, 8] float 0/1 bit-vectors of fp8 e4m3 (order S,E3..E0,M2,M1,M0)
//   out : [N, 32] float 0/1 bit-vector of fp32(A_val * B_val), MSB (sign) first.
//
// Pure HBM streaming (256 MB in, 512 MB out). R3: persistent grid (6 blocks x
// 148 SMs) + double-buffered pipeline: prefetch LDGs for the next tile are
// issued before the store loop of the current tile, so every SM keeps read
// and write streams simultaneously in flight; no wave transitions, no tail.
// 128-bit ld/st (R2 showed 256-bit regresses on this chip).

#define THREADS 256
#define GRID 888          // 6 blocks/SM * 148 SMs (fits at ~40 regs)

static __device__ __forceinline__ uint32_t bit_of(float f) {
    // inputs are exactly 0.0f (0x00000000) or 1.0f (0x3F800000): test bit 23
    return (__float_as_uint(f) >> 23) & 1u;
}

static __device__ __forceinline__ float decode_e4m3(float4 lo, float4 hi) {
    // lo = {S, E3, E2, E1}, hi = {E0, M2, M1, M0}
    uint32_t s = bit_of(lo.x);
    uint32_t e = (bit_of(lo.y) << 3) | (bit_of(lo.z) << 2) |
                 (bit_of(lo.w) << 1) |  bit_of(hi.x);
    uint32_t m = (bit_of(hi.y) << 2) | (bit_of(hi.z) << 1) | bit_of(hi.w);
    // normal: (8+m)*2^(e-10); subnormal: m*2^-9
    uint32_t M = e ? (8u + m) : m;
    int      E = e ? ((int)e - 10) : -9;
    float mag = (float)(int)M * __int_as_float((E + 127) << 23);
    // OR sign in so zero products keep their sign bit (-0.0 matters to the
    // reference's fp32 bitcast)
    return __uint_as_float(__float_as_uint(mag) | (s << 31));
}

__global__ void __launch_bounds__(THREADS)
spike_fp8_mul_kernel(const float4* __restrict__ A4,
                     const float4* __restrict__ B4,
                     float4* __restrict__ out4,
                     int nrows) {
    __shared__ uint32_t sh[2][THREADS];

    const int tid    = threadIdx.x;
    const int ntiles = (nrows + THREADS - 1) / THREADS;
    const int stride = gridDim.x;

    int tile = blockIdx.x;
    if (tile >= ntiles) return;

    // prologue: load tile 0 of this block
    float4 a0, a1, b0, b1;
    bool v;
    {
        int row = tile * THREADS + tid;
        v = row < nrows;
        if (v) {
            size_t r2 = 2 * (size_t)row;
            a0 = __ldcs(&A4[r2]); a1 = __ldcs(&A4[r2 + 1]);
            b0 = __ldcs(&B4[r2]); b1 = __ldcs(&B4[r2 + 1]);
        }
    }

    const int g_shift = 28 - ((tid & 7) << 2);   // loop-invariant
    int buf = 0;

    while (true) {
        // decode current tile into SMEM
        uint32_t p = 0;
        if (v) {
            float va = decode_e4m3(a0, a1);
            float vb = decode_e4m3(b0, b1);
            p = __float_as_uint(va * vb);        // exact; IEEE sign-of-zero
        }
        sh[buf][tid] = p;

        // prefetch next tile BEFORE the barrier/store loop so the LDGs are
        // in flight while this tile is being written out
        const int ntile = tile + stride;
        bool nv = false;
        if (ntile < ntiles) {
            int row = ntile * THREADS + tid;
            nv = row < nrows;
            if (nv) {
                size_t r2 = 2 * (size_t)row;
                a0 = __ldcs(&A4[r2]); a1 = __ldcs(&A4[r2 + 1]);
                b0 = __ldcs(&B4[r2]); b1 = __ldcs(&B4[r2 + 1]);
            }
        }
        __syncthreads();

        // store current tile: 256 rows * 32 floats = 2048 float4, coalesced.
        // float4 q: row = q>>3, bit group g = q&7 holds product bits
        // [31-4g .. 28-4g], MSB-first.
        const int rows_left = nrows - tile * THREADS;         // > 0
        const int q_limit   = rows_left >= THREADS ? THREADS * 8
                                                   : rows_left * 8;
        float4* blk_out = out4 + (size_t)tile * (THREADS * 8);

#pragma unroll
        for (int k = 0; k < 8; k++) {
            int q = k * THREADS + tid;
            if (q < q_limit) {
                uint32_t t = sh[buf][q >> 3] >> g_shift;      // 8-lane bcast
                float4 o;
                o.x = __uint_as_float(((t >> 3) & 1u) * 0x3F800000u);
                o.y = __uint_as_float(((t >> 2) & 1u) * 0x3F800000u);
                o.z = __uint_as_float(((t >> 1) & 1u) * 0x3F800000u);
                o.w = __uint_as_float(( t        & 1u) * 0x3F800000u);
                __stcs(&blk_out[q], o);
            }
        }

        if (ntile >= ntiles) break;
        tile = ntile;
        v = nv;
        buf ^= 1;
        // no extra barrier needed: next iteration writes the other buffer;
        // reuse of this buffer happens only after the next iteration's
        // __syncthreads
    }
}

extern "C" void kernel_launch(void* const* d_in, const int* in_sizes, int n_in,
                              void* d_out, int out_size) {
    const float4* A4 = (const float4*)d_in[0];
    const float4* B4 = (const float4*)d_in[1];
    float4* out4 = (float4*)d_out;

    int nrows  = in_sizes[0] / 8;
    int ntiles = (nrows + THREADS - 1) / THREADS;
    int blocks = ntiles < GRID ? ntiles : GRID;
    spike_fp8_mul_kernel<<<blocks, THREADS>>>(A4, B4, out4, nrows);
}

// round 6
// speedup vs baseline: 1.1645x; 1.1645x over previous
#include <cuda_runtime.h>
#include <cstdint>

// SpikeFP8MulToFP32:
//   A, B: [N, 8] float 0/1 bit-vectors of fp8 e4m3 (order S,E3..E0,M2,M1,M0)
//   out : [N, 32] float 0/1 bit-vector of fp32(A_val * B_val), MSB (sign) first.
//
// Pure HBM streaming (256 MB in, 512 MB out). Learned so far:
//   R1 (grid 16384, 256 thr, SMEM stage, 128-bit):    115.9us, DRAM 78.8%  <- best
//   R2 (256-bit v8 ld/st):                            121.1us  (wavefront cap is
//                                                      width-independent; less MLP)
//   R3 (persistent 888-block pipeline):               132.1us  (occupancy loss +
//                                                      barrier-coupled phases)
//   R4/R5: broker infra failures, no data — resubmitting unchanged.
// Design: R1 structure, but replace SMEM+__syncthreads with warp shuffles.
// The cross-thread redistribution is only within 8-lane groups, so
// __shfl_sync does it warp-locally: no barrier, no SMEM, each warp streams
// load->decode->store independently (no block-wide phase lockstep).

#define THREADS 256

static __device__ __forceinline__ uint32_t bit_of(float f) {
    // inputs are exactly 0.0f (0x00000000) or 1.0f (0x3F800000): test bit 23
    return (__float_as_uint(f) >> 23) & 1u;
}

static __device__ __forceinline__ float decode_e4m3(float4 lo, float4 hi) {
    // lo = {S, E3, E2, E1}, hi = {E0, M2, M1, M0}
    uint32_t s = bit_of(lo.x);
    uint32_t e = (bit_of(lo.y) << 3) | (bit_of(lo.z) << 2) |
                 (bit_of(lo.w) << 1) |  bit_of(hi.x);
    uint32_t m = (bit_of(hi.y) << 2) | (bit_of(hi.z) << 1) | bit_of(hi.w);
    // normal: (8+m)*2^(e-10); subnormal: m*2^-9
    uint32_t M = e ? (8u + m) : m;
    int      E = e ? ((int)e - 10) : -9;
    float mag = (float)(int)M * __int_as_float((E + 127) << 23);
    // OR sign in so zero products keep their sign bit (-0.0 matters to the
    // reference's fp32 bitcast)
    return __uint_as_float(__float_as_uint(mag) | (s << 31));
}

__global__ void __launch_bounds__(THREADS)
spike_fp8_mul_kernel(const float4* __restrict__ A4,
                     const float4* __restrict__ B4,
                     float4* __restrict__ out4,
                     int nrows) {
    const int tid  = threadIdx.x;
    const int lane = tid & 31;
    const int row  = blockIdx.x * THREADS + tid;

    // ---- load + decode: one row per thread, 4 independent LDG.128
    uint32_t p = 0;
    if (row < nrows) {
        size_t r2 = 2 * (size_t)row;
        float4 a0 = __ldcs(&A4[r2]);
        float4 a1 = __ldcs(&A4[r2 + 1]);
        float4 b0 = __ldcs(&B4[r2]);
        float4 b1 = __ldcs(&B4[r2 + 1]);
        p = __float_as_uint(decode_e4m3(a0, a1) * decode_e4m3(b0, b1));
    }

    // ---- store: warp covers 32 rows -> 4KB contiguous output.
    // Iteration k: warp writes float4s [k*32 .. k*32+31] of its span (512B,
    // fully coalesced). float4 index q = k*32 + lane within the warp span:
    //   source row-in-warp = q>>3 = k*4 + (lane>>3)
    //   bit group g = q&7 = lane&7  (k*32 is 0 mod 8) -> loop-invariant shift
    // Redistribution is warp-local: shuffle replaces SMEM + __syncthreads.
    const int warp_row0 = row & ~31;                  // first row of warp span
    float4* wout = out4 + (size_t)warp_row0 * 8;
    const int rows_left  = nrows - warp_row0;
    const int q_limit    = rows_left >= 32 ? 256 : rows_left * 8;
    const int g_shift    = 28 - ((lane & 7) << 2);
    const int src_base   = lane >> 3;

#pragma unroll
    for (int k = 0; k < 8; k++) {
        uint32_t ps = __shfl_sync(0xffffffffu, p, k * 4 + src_base);
        int q = k * 32 + lane;
        if (q < q_limit) {
            uint32_t t = ps >> g_shift;               // bits of group g
            float4 o;
            o.x = __uint_as_float(((t >> 3) & 1u) * 0x3F800000u);
            o.y = __uint_as_float(((t >> 2) & 1u) * 0x3F800000u);
            o.z = __uint_as_float(((t >> 1) & 1u) * 0x3F800000u);
            o.w = __uint_as_float(( t        & 1u) * 0x3F800000u);
            __stcs(&wout[q], o);
        }
    }
}

extern "C" void kernel_launch(void* const* d_in, const int* in_sizes, int n_in,
                              void* d_out, int out_size) {
    const float4* A4 = (const float4*)d_in[0];
    const float4* B4 = (const float4*)d_in[1];
    float4* out4 = (float4*)d_out;

    int nrows  = in_sizes[0] / 8;
    int blocks = (nrows + THREADS - 1) / THREADS;
    spike_fp8_mul_kernel<<<blocks, THREADS>>>(A4, B4, out4, nrows);
}